// round 2
// baseline (speedup 1.0000x reference)
#include <cuda_runtime.h>
#include <math.h>

#define Bsz 32
#define Nn  1024
#define Dd  128
#define NROWS (Bsz*Nn)

// Scratch (device globals: allocation-free rule)
__device__ float g_itr[NROWS * Dd];   // itr_attn output, 16.8 MB
__device__ float g_qa[NROWS];         // per-token column bias qa[j] = P[j].wa

// ---------------------------------------------------------------------------
// qa kernel: one warp per token row, qa = dot(P[row,:], w[0:128])
// ---------------------------------------------------------------------------
__global__ void qa_kernel(const float* __restrict__ P, const float* __restrict__ w) {
    int row  = blockIdx.x * blockDim.y + threadIdx.y;
    int lane = threadIdx.x;
    if (row >= NROWS) return;
    const float* p = P + (size_t)row * Dd;
    float s = 0.f;
    #pragma unroll
    for (int k = lane; k < Dd; k += 32) s += p[k] * w[k];
    #pragma unroll
    for (int off = 16; off > 0; off >>= 1) s += __shfl_xor_sync(0xffffffffu, s, off);
    if (lane == 0) g_qa[row] = s;
}

// ---------------------------------------------------------------------------
// Flash-attention kernel.
// S[i,j] = (P[i]*wc) . P[j] + qa[j]   (row bias (P@wb)[i] cancels in softmax)
// itr = softmax_j(S) @ P
// Tile: BM=128 query rows x BN=128 keys, D=128. 256 threads (16x16),
// 8x8 register micro-tile; cols strided by 16 for conflict-free smem reads.
// ---------------------------------------------------------------------------
#define BM  128
#define BN  128
#define LDP 132   // padded smem row stride (floats): 132 % 32 == 4 -> 2-way max

__global__ __launch_bounds__(256, 1)
void flash_kernel(const float* __restrict__ P, const float* __restrict__ w) {
    extern __shared__ float sm[];
    float* Qs  = sm;                   // BM*LDP
    float* Ks  = Qs + BM * LDP;        // BN*LDP  (K tile == V tile, since K=V=P)
    float* SAs = Ks + BN * LDP;        // BM*LDP
    float* qas = SAs + BM * LDP;       // BN
    float* ms  = qas + BN;             // BM running max
    float* ls  = ms + BM;              // BM running sum

    const int b   = blockIdx.y;
    const int i0  = blockIdx.x * BM;
    const int tid = threadIdx.x;
    const int tx  = tid & 15;
    const int ty  = tid >> 4;

    // Load Q tile = P[b, i0:i0+BM, :] * wc  (wc = w + 2*D)
    {
        const float4* wc4 = (const float4*)(w + 2 * Dd);
        const float4* Pg  = (const float4*)(P + ((size_t)b * Nn + i0) * Dd);
        #pragma unroll
        for (int t = 0; t < (BM * (Dd / 4)) / 256; t++) {
            int idx = tid + t * 256;
            int r = idx >> 5, c4 = idx & 31;
            float4 v  = Pg[r * (Dd / 4) + c4];
            float4 wv = wc4[c4];
            v.x *= wv.x; v.y *= wv.y; v.z *= wv.z; v.w *= wv.w;
            *(float4*)(Qs + r * LDP + c4 * 4) = v;
        }
    }
    for (int r = tid; r < BM; r += 256) { ms[r] = -1e30f; ls[r] = 0.f; }

    float O[8][8];
    #pragma unroll
    for (int y = 0; y < 8; y++)
        #pragma unroll
        for (int u = 0; u < 8; u++) O[y][u] = 0.f;

    for (int j0 = 0; j0 < Nn; j0 += BN) {
        __syncthreads();  // previous PV done before overwriting K tile
        {
            const float4* Kg = (const float4*)(P + ((size_t)b * Nn + j0) * Dd);
            #pragma unroll
            for (int t = 0; t < (BN * (Dd / 4)) / 256; t++) {
                int idx = tid + t * 256;
                int r = idx >> 5, c4 = idx & 31;
                *(float4*)(Ks + r * LDP + c4 * 4) = Kg[r * (Dd / 4) + c4];
            }
            if (tid < BN) qas[tid] = g_qa[(size_t)b * Nn + j0 + tid];
        }
        __syncthreads();

        // ---- S = Q @ K^T  (rows r=ty*8+y, cols c=tx+16*x) ----
        float S[8][8];
        #pragma unroll
        for (int y = 0; y < 8; y++)
            #pragma unroll
            for (int x = 0; x < 8; x++) S[y][x] = 0.f;

        #pragma unroll 1
        for (int k = 0; k < Dd; k += 4) {
            float4 q[8];
            #pragma unroll
            for (int y = 0; y < 8; y++)
                q[y] = *(const float4*)(Qs + (ty * 8 + y) * LDP + k);
            #pragma unroll
            for (int x = 0; x < 8; x++) {
                float4 kv = *(const float4*)(Ks + (tx + 16 * x) * LDP + k);
                #pragma unroll
                for (int y = 0; y < 8; y++) {
                    S[y][x] += q[y].x * kv.x;
                    S[y][x] += q[y].y * kv.y;
                    S[y][x] += q[y].z * kv.z;
                    S[y][x] += q[y].w * kv.w;
                }
            }
        }

        // ---- online softmax (add column bias qa[j]) ----
        #pragma unroll
        for (int y = 0; y < 8; y++) {
            const int r = ty * 8 + y;
            float mx = -1e30f;
            #pragma unroll
            for (int x = 0; x < 8; x++) {
                S[y][x] += qas[tx + 16 * x];
                mx = fmaxf(mx, S[y][x]);
            }
            #pragma unroll
            for (int off = 1; off < 16; off <<= 1)
                mx = fmaxf(mx, __shfl_xor_sync(0xffffffffu, mx, off));
            float mold  = ms[r];
            float mnew  = fmaxf(mold, mx);
            float alpha = __expf(mold - mnew);
            float ssum  = 0.f;
            #pragma unroll
            for (int x = 0; x < 8; x++) {
                float pv = __expf(S[y][x] - mnew);
                S[y][x] = pv;
                ssum += pv;
            }
            #pragma unroll
            for (int off = 1; off < 16; off <<= 1)
                ssum += __shfl_xor_sync(0xffffffffu, ssum, off);
            if (tx == 0) { ms[r] = mnew; ls[r] = ls[r] * alpha + ssum; }
            #pragma unroll
            for (int u = 0; u < 8; u++) O[y][u] *= alpha;
            #pragma unroll
            for (int x = 0; x < 8; x++)
                SAs[r * LDP + tx + 16 * x] = S[y][x];
        }
        // No cross-warp dependency between softmax and PV: each warp-group
        // reads only its own SA rows, V tile (Ks) is read-only here.

        // ---- O += SA @ V  (V tile == Ks) ----
        #pragma unroll 1
        for (int j = 0; j < BN; j += 4) {
            float4 a[8];
            #pragma unroll
            for (int y = 0; y < 8; y++)
                a[y] = *(const float4*)(SAs + (ty * 8 + y) * LDP + j);
            #pragma unroll
            for (int jj = 0; jj < 4; jj++) {
                float v[8];
                #pragma unroll
                for (int u = 0; u < 8; u++)
                    v[u] = Ks[(j + jj) * LDP + tx + 16 * u];
                #pragma unroll
                for (int y = 0; y < 8; y++) {
                    float av = (jj == 0) ? a[y].x : (jj == 1) ? a[y].y
                             : (jj == 2) ? a[y].z : a[y].w;
                    #pragma unroll
                    for (int u = 0; u < 8; u++) O[y][u] += av * v[u];
                }
            }
        }
    }
    __syncthreads();

    // Normalize and store itr
    #pragma unroll
    for (int y = 0; y < 8; y++) {
        const int r = ty * 8 + y;
        float inv = 1.f / ls[r];
        float* dst = g_itr + ((size_t)b * Nn + i0 + r) * Dd;
        #pragma unroll
        for (int u = 0; u < 8; u++)
            dst[tx + 16 * u] = O[y][u] * inv;
    }
}

// ---------------------------------------------------------------------------
// Fused gated MLP: X = [P, itr] (K=256), three GEMMs to D=128 each + epilogue
// out = sigmoid(X@w2+b2) * P + sigmoid(X@w3+b3) * tanh(X@w1+b1)
// Block: 64 rows x 128 cols, 256 threads, 4x8 micro-tile per weight.
// ---------------------------------------------------------------------------
#define MBM 64
#define LDX 68

__global__ __launch_bounds__(256, 1)
void mlp_kernel(const float* __restrict__ P,
                const float* __restrict__ w1, const float* __restrict__ w2,
                const float* __restrict__ w3,
                const float* __restrict__ b1, const float* __restrict__ b2,
                const float* __restrict__ b3,
                float* __restrict__ out) {
    extern __shared__ float sm[];
    float* Xs  = sm;                 // MBM * LDX
    float* W1s = Xs + MBM * LDX;     // 64 * 128
    float* W2s = W1s + 64 * 128;
    float* W3s = W2s + 64 * 128;

    const int row0 = blockIdx.x * MBM;
    const int tid  = threadIdx.x;
    const int tx   = tid & 15;
    const int ty   = tid >> 4;

    float a1[4][8], a2[4][8], a3[4][8];
    #pragma unroll
    for (int y = 0; y < 4; y++)
        #pragma unroll
        for (int u = 0; u < 8; u++) { a1[y][u] = 0.f; a2[y][u] = 0.f; a3[y][u] = 0.f; }

    for (int kc = 0; kc < 4; kc++) {
        __syncthreads();
        // X chunk: k in [kc*64, kc*64+64). Chunks 0,1 come from P; 2,3 from itr.
        const float* Xbase = (kc < 2)
            ? (P     + (size_t)row0 * Dd + kc * 64)
            : (g_itr + (size_t)row0 * Dd + (kc - 2) * 64);
        #pragma unroll
        for (int t = 0; t < 4; t++) {            // 64 rows * 16 float4 = 1024
            int idx = tid + t * 256;
            int r = idx >> 4, c4 = idx & 15;
            float4 v = *(const float4*)(Xbase + (size_t)r * Dd + c4 * 4);
            *(float4*)(Xs + r * LDX + c4 * 4) = v;
        }
        const float4* w1g = (const float4*)(w1 + (size_t)kc * 64 * Dd);
        const float4* w2g = (const float4*)(w2 + (size_t)kc * 64 * Dd);
        const float4* w3g = (const float4*)(w3 + (size_t)kc * 64 * Dd);
        #pragma unroll
        for (int t = 0; t < 8; t++) {            // 64*128/4 = 2048 float4
            int idx = tid + t * 256;
            ((float4*)W1s)[idx] = w1g[idx];
            ((float4*)W2s)[idx] = w2g[idx];
            ((float4*)W3s)[idx] = w3g[idx];
        }
        __syncthreads();

        #pragma unroll 2
        for (int kk = 0; kk < 64; kk++) {
            float xv[4];
            #pragma unroll
            for (int y = 0; y < 4; y++) xv[y] = Xs[(ty * 4 + y) * LDX + kk];

            float4 wA = *(const float4*)(W1s + kk * 128 + tx * 8);
            float4 wB = *(const float4*)(W1s + kk * 128 + tx * 8 + 4);
            #pragma unroll
            for (int y = 0; y < 4; y++) {
                a1[y][0] += xv[y] * wA.x; a1[y][1] += xv[y] * wA.y;
                a1[y][2] += xv[y] * wA.z; a1[y][3] += xv[y] * wA.w;
                a1[y][4] += xv[y] * wB.x; a1[y][5] += xv[y] * wB.y;
                a1[y][6] += xv[y] * wB.z; a1[y][7] += xv[y] * wB.w;
            }
            wA = *(const float4*)(W2s + kk * 128 + tx * 8);
            wB = *(const float4*)(W2s + kk * 128 + tx * 8 + 4);
            #pragma unroll
            for (int y = 0; y < 4; y++) {
                a2[y][0] += xv[y] * wA.x; a2[y][1] += xv[y] * wA.y;
                a2[y][2] += xv[y] * wA.z; a2[y][3] += xv[y] * wA.w;
                a2[y][4] += xv[y] * wB.x; a2[y][5] += xv[y] * wB.y;
                a2[y][6] += xv[y] * wB.z; a2[y][7] += xv[y] * wB.w;
            }
            wA = *(const float4*)(W3s + kk * 128 + tx * 8);
            wB = *(const float4*)(W3s + kk * 128 + tx * 8 + 4);
            #pragma unroll
            for (int y = 0; y < 4; y++) {
                a3[y][0] += xv[y] * wA.x; a3[y][1] += xv[y] * wA.y;
                a3[y][2] += xv[y] * wA.z; a3[y][3] += xv[y] * wA.w;
                a3[y][4] += xv[y] * wB.x; a3[y][5] += xv[y] * wB.y;
                a3[y][6] += xv[y] * wB.z; a3[y][7] += xv[y] * wB.w;
            }
        }
    }

    // Epilogue: z=tanh(..w1+b1), r=sigmoid(..w2+b2), f=sigmoid(..w3+b3)
    #pragma unroll
    for (int y = 0; y < 4; y++) {
        int r = row0 + ty * 4 + y;
        const float* prow = P + (size_t)r * Dd;
        float* orow = out + (size_t)r * Dd;
        #pragma unroll
        for (int u = 0; u < 8; u++) {
            int c = tx * 8 + u;
            float z  = tanhf(a1[y][u] + b1[c]);
            float rr = 1.f / (1.f + __expf(-(a2[y][u] + b2[c])));
            float ff = 1.f / (1.f + __expf(-(a3[y][u] + b3[c])));
            orow[c] = rr * prow[c] + ff * z;
        }
    }
}

// ---------------------------------------------------------------------------
extern "C" void kernel_launch(void* const* d_in, const int* in_sizes, int n_in,
                              void* d_out, int out_size) {
    const float* P  = (const float*)d_in[0];
    const float* w  = (const float*)d_in[1];
    const float* w1 = (const float*)d_in[2];
    const float* w2 = (const float*)d_in[3];
    const float* w3 = (const float*)d_in[4];
    const float* b1 = (const float*)d_in[5];
    const float* b2 = (const float*)d_in[6];
    const float* b3 = (const float*)d_in[7];
    float* out = (float*)d_out;

    const size_t flash_smem = (size_t)(3 * BM * LDP + BN + 2 * BM) * sizeof(float); // 204288 B
    const size_t mlp_smem   = (size_t)(MBM * LDX + 3 * 64 * 128) * sizeof(float);   // 115712 B
    cudaFuncSetAttribute(flash_kernel, cudaFuncAttributeMaxDynamicSharedMemorySize,
                         (int)flash_smem);
    cudaFuncSetAttribute(mlp_kernel, cudaFuncAttributeMaxDynamicSharedMemorySize,
                         (int)mlp_smem);

    dim3 qb(32, 8);
    qa_kernel<<<NROWS / 8, qb>>>(P, w);

    dim3 fg(Nn / BM, Bsz);
    flash_kernel<<<fg, 256, flash_smem>>>(P, w);

    mlp_kernel<<<NROWS / MBM, 256, mlp_smem>>>(P, w1, w2, w3, b1, b2, b3, out);
}

// round 4
// speedup vs baseline: 2.1575x; 2.1575x over previous
#include <cuda_runtime.h>
#include <cuda_bf16.h>
#include <cstdint>
#include <math.h>

#define Bsz 32
#define Nn  1024
#define Dd  128
#define NROWS (Bsz*Nn)

// Scratch (device globals: allocation-free rule)
__device__ float g_itr[NROWS * Dd];          // itr_attn fp32
__device__ float g_qa[NROWS];                // qa[j] = P[j].wa
__device__ uint32_t g_whu[3 * 16384];        // weights bf16x2 hi (3 x 256x128)
__device__ uint32_t g_wlu[3 * 16384];        // weights bf16x2 lo

// ===========================================================================
// helpers
// ===========================================================================
__device__ __forceinline__ uint32_t smem_u32(const void* p) {
    uint32_t a;
    asm("{ .reg .u64 t; cvta.to.shared.u64 t, %1; cvt.u32.u64 %0, t; }" : "=r"(a) : "l"(p));
    return a;
}
__device__ __forceinline__ void ldsm_x4(uint32_t a[4], uint32_t addr) {
    asm volatile("ldmatrix.sync.aligned.m8n8.x4.shared.b16 {%0,%1,%2,%3}, [%4];"
        : "=r"(a[0]), "=r"(a[1]), "=r"(a[2]), "=r"(a[3]) : "r"(addr));
}
__device__ __forceinline__ void ldsm_x2(uint32_t b[2], uint32_t addr) {
    asm volatile("ldmatrix.sync.aligned.m8n8.x2.shared.b16 {%0,%1}, [%2];"
        : "=r"(b[0]), "=r"(b[1]) : "r"(addr));
}
__device__ __forceinline__ void ldsm_x2t(uint32_t b[2], uint32_t addr) {
    asm volatile("ldmatrix.sync.aligned.m8n8.x2.trans.shared.b16 {%0,%1}, [%2];"
        : "=r"(b[0]), "=r"(b[1]) : "r"(addr));
}
__device__ __forceinline__ void mma_bf16(float c[4], const uint32_t a[4], const uint32_t b[2]) {
    asm volatile("mma.sync.aligned.m16n8k16.row.col.f32.bf16.bf16.f32 "
        "{%0,%1,%2,%3}, {%4,%5,%6,%7}, {%8,%9}, {%0,%1,%2,%3};"
        : "+f"(c[0]), "+f"(c[1]), "+f"(c[2]), "+f"(c[3])
        : "r"(a[0]), "r"(a[1]), "r"(a[2]), "r"(a[3]), "r"(b[0]), "r"(b[1]));
}
// pack two floats -> bf16x2 (hi) and residual bf16x2 (lo)
__device__ __forceinline__ void split2(float x, float y, uint32_t& h, uint32_t& l) {
    __nv_bfloat16 hx = __float2bfloat16_rn(x), hy = __float2bfloat16_rn(y);
    __nv_bfloat162 hv = __halves2bfloat162(hx, hy);   // low = x
    h = *(uint32_t*)&hv;
    __nv_bfloat162 lv = __halves2bfloat162(
        __float2bfloat16_rn(x - __bfloat162float(hx)),
        __float2bfloat16_rn(y - __bfloat162float(hy)));
    l = *(uint32_t*)&lv;
}

// ===========================================================================
// prep kernels
// ===========================================================================
__global__ void qa_kernel(const float* __restrict__ P, const float* __restrict__ w) {
    int row  = blockIdx.x * blockDim.y + threadIdx.y;
    int lane = threadIdx.x;
    if (row >= NROWS) return;
    const float* p = P + (size_t)row * Dd;
    float s = 0.f;
    #pragma unroll
    for (int k = lane; k < Dd; k += 32) s += p[k] * w[k];
    #pragma unroll
    for (int off = 16; off > 0; off >>= 1) s += __shfl_xor_sync(0xffffffffu, s, off);
    if (lane == 0) g_qa[row] = s;
}

// split w1/w2/w3 (256x128 f32, n-contiguous) into bf16x2 hi/lo pairs along n
__global__ void wsplit_kernel(const float* __restrict__ w1, const float* __restrict__ w2,
                              const float* __restrict__ w3) {
    int idx = blockIdx.x * 256 + threadIdx.x;    // 16384 u32 per weight
    if (idx >= 16384) return;
    const float* srcs[3] = { w1, w2, w3 };
    #pragma unroll
    for (int g = 0; g < 3; g++) {
        float x = srcs[g][idx * 2], y = srcs[g][idx * 2 + 1];
        uint32_t h, l;
        split2(x, y, h, l);
        g_whu[g * 16384 + idx] = h;
        g_wlu[g * 16384 + idx] = l;
    }
}

// ===========================================================================
// HMMA flash attention.
// S = (P*wc) @ P^T (+qa[j] col bias; row bias cancels); no-max softmax;
// probs stay in registers (S frag layout == PV A frag layout); K tile doubles
// as V via ldmatrix.trans. All GEMMs bf16 hi/lo 3-term split.
// ===========================================================================
#define LDT 136                              // bf16 tile stride (conflict-free)
#define FS_QH 0
#define FS_QL 34816
#define FS_KH 69632
#define FS_KL 104448
#define FS_QA 139264
#define FS_TOT (FS_QA + 512)

__global__ __launch_bounds__(256, 1)
void flash_hmma(const float* __restrict__ P, const float* __restrict__ w) {
    extern __shared__ char smem[];
    const uint32_t sb = smem_u32(smem);
    float* qas = (float*)(smem + FS_QA);
    const int tid = threadIdx.x, lane = tid & 31, wm = tid >> 5;
    const int b = blockIdx.y, i0 = blockIdx.x * 128;
    const int lg = lane >> 3, li = lane & 7;
    const int qr = lane >> 2, qc2 = (lane & 3) << 1;

    // ---- convert Q = P*wc into bf16 hi/lo tiles ----
    {
        const int r = tid >> 1, ch = (tid & 1) << 6;
        const float4* src = (const float4*)(P + ((size_t)(b * Nn + i0 + r)) * Dd + ch);
        const float4* wc4 = (const float4*)(w + 2 * Dd + ch);
        #pragma unroll
        for (int c4 = 0; c4 < 16; c4++) {
            float4 v = src[c4], wv = wc4[c4];
            int c0 = ch + c4 * 4;
            uint32_t h, l;
            split2(v.x * wv.x, v.y * wv.y, h, l);
            *(uint32_t*)(smem + FS_QH + (r * LDT + c0) * 2) = h;
            *(uint32_t*)(smem + FS_QL + (r * LDT + c0) * 2) = l;
            split2(v.z * wv.z, v.w * wv.w, h, l);
            *(uint32_t*)(smem + FS_QH + (r * LDT + c0 + 2) * 2) = h;
            *(uint32_t*)(smem + FS_QL + (r * LDT + c0 + 2) * 2) = l;
        }
    }

    float o[16][4];
    #pragma unroll
    for (int n = 0; n < 16; n++)
        #pragma unroll
        for (int u = 0; u < 4; u++) o[n][u] = 0.f;
    float lsum0 = 0.f, lsum1 = 0.f;

    for (int j0 = 0; j0 < Nn; j0 += 128) {
        __syncthreads();   // prior compute done (and Q visible on iter 0)
        // ---- convert K tile (token-major bf16 hi/lo) ----
        {
            const int r = tid >> 1, ch = (tid & 1) << 6;
            const float4* src = (const float4*)(P + ((size_t)(b * Nn + j0 + r)) * Dd + ch);
            #pragma unroll
            for (int c4 = 0; c4 < 16; c4++) {
                float4 v = src[c4];
                int c0 = ch + c4 * 4;
                uint32_t h, l;
                split2(v.x, v.y, h, l);
                *(uint32_t*)(smem + FS_KH + (r * LDT + c0) * 2) = h;
                *(uint32_t*)(smem + FS_KL + (r * LDT + c0) * 2) = l;
                split2(v.z, v.w, h, l);
                *(uint32_t*)(smem + FS_KH + (r * LDT + c0 + 2) * 2) = h;
                *(uint32_t*)(smem + FS_KL + (r * LDT + c0 + 2) * 2) = l;
            }
            if (tid < 128) qas[tid] = g_qa[(size_t)b * Nn + j0 + tid];
        }
        __syncthreads();

        // ---- S = Q @ K^T : 3 split terms ----
        float s[16][4];
        #pragma unroll
        for (int n = 0; n < 16; n++)
            #pragma unroll
            for (int u = 0; u < 4; u++) s[n][u] = 0.f;

        #pragma unroll 1
        for (int sp = 0; sp < 3; sp++) {
            const uint32_t Ab = sb + ((sp == 2) ? FS_QL : FS_QH);
            const uint32_t Bb = sb + ((sp == 1) ? FS_KL : FS_KH);
            uint32_t a[8][4];
            #pragma unroll
            for (int kt = 0; kt < 8; kt++) {
                int row = wm * 16 + ((lg & 1) << 3) + li;
                int col = kt * 16 + ((lg >> 1) << 3);
                ldsm_x4(a[kt], Ab + (row * LDT + col) * 2);
            }
            #pragma unroll
            for (int jn = 0; jn < 16; jn++) {
                #pragma unroll
                for (int kt = 0; kt < 8; kt++) {
                    uint32_t bf[2];
                    int row = jn * 8 + li;
                    int col = kt * 16 + ((lg & 1) << 3);
                    ldsm_x2(bf, Bb + (row * LDT + col) * 2);
                    mma_bf16(s[jn], a[kt], bf);
                }
            }
        }

        // ---- exp (+qa col bias), pack probs into PV A-fragments ----
        uint32_t ph[8][4], pl[8][4];
        #pragma unroll
        for (int jn = 0; jn < 16; jn++) {
            int cb = jn * 8 + qc2;
            float q0 = qas[cb], q1 = qas[cb + 1];
            float p0 = __expf(s[jn][0] + q0);
            float p1 = __expf(s[jn][1] + q1);
            float p2 = __expf(s[jn][2] + q0);
            float p3 = __expf(s[jn][3] + q1);
            lsum0 += p0 + p1;
            lsum1 += p2 + p3;
            int kt = jn >> 1, hv = (jn & 1) << 1;
            split2(p0, p1, ph[kt][hv],     pl[kt][hv]);
            split2(p2, p3, ph[kt][hv + 1], pl[kt][hv + 1]);
        }

        // ---- O += P @ V (V tile == K tile via trans ldmatrix) ----
        #pragma unroll 1
        for (int sp = 0; sp < 3; sp++) {
            const uint32_t (*A)[4] = (sp == 2) ? pl : ph;
            const uint32_t Bb = sb + ((sp == 1) ? FS_KL : FS_KH);
            #pragma unroll
            for (int dn = 0; dn < 16; dn++) {
                #pragma unroll
                for (int kt = 0; kt < 8; kt++) {
                    uint32_t bf[2];
                    int row = kt * 16 + ((lg & 1) << 3) + li;
                    int col = dn * 8;
                    ldsm_x2t(bf, Bb + (row * LDT + col) * 2);
                    mma_bf16(o[dn], A[kt], bf);
                }
            }
        }
    }

    // ---- normalize, store itr ----
    lsum0 += __shfl_xor_sync(0xffffffffu, lsum0, 1);
    lsum0 += __shfl_xor_sync(0xffffffffu, lsum0, 2);
    lsum1 += __shfl_xor_sync(0xffffffffu, lsum1, 1);
    lsum1 += __shfl_xor_sync(0xffffffffu, lsum1, 2);
    float inv0 = 1.f / lsum0, inv1 = 1.f / lsum1;
    const size_t r0 = (size_t)b * Nn + i0 + wm * 16 + qr;
    #pragma unroll
    for (int dn = 0; dn < 16; dn++) {
        int c = dn * 8 + qc2;
        *(float2*)(g_itr + r0 * Dd + c)       = make_float2(o[dn][0] * inv0, o[dn][1] * inv0);
        *(float2*)(g_itr + (r0 + 8) * Dd + c) = make_float2(o[dn][2] * inv1, o[dn][3] * inv1);
    }
}

// ===========================================================================
// HMMA fused gated MLP: X=[P,itr] (64 rows/CTA, K=256), 3 weights, 3-term split
// ===========================================================================
#define XLD 264
#define MS_XH 0
#define MS_XL 33792
#define MS_WH 67584
#define MS_WL 137216
#define MS_TOT 206848

__global__ __launch_bounds__(256, 1)
void mlp_hmma(const float* __restrict__ P,
              const float* __restrict__ b1, const float* __restrict__ b2,
              const float* __restrict__ b3, float* __restrict__ out) {
    extern __shared__ char smem[];
    const uint32_t sb = smem_u32(smem);
    const int tid = threadIdx.x, lane = tid & 31, wid = tid >> 5;
    const int wm = wid & 3, wn = wid >> 2;
    const int lg = lane >> 3, li = lane & 7;
    const int qr = lane >> 2, qc2 = (lane & 3) << 1;
    const int row0 = blockIdx.x * 64;

    // ---- convert X = [P | itr] into bf16 hi/lo (64 x 256) ----
    {
        const int r = tid >> 2, q = tid & 3;
        const int c0 = q * 64;
        const float* base = (q < 2)
            ? (P     + ((size_t)(row0 + r)) * Dd + q * 64)
            : (g_itr + ((size_t)(row0 + r)) * Dd + (q - 2) * 64);
        const float4* src = (const float4*)base;
        #pragma unroll
        for (int c4 = 0; c4 < 16; c4++) {
            float4 v = src[c4];
            int c = c0 + c4 * 4;
            uint32_t h, l;
            split2(v.x, v.y, h, l);
            *(uint32_t*)(smem + MS_XH + (r * XLD + c) * 2) = h;
            *(uint32_t*)(smem + MS_XL + (r * XLD + c) * 2) = l;
            split2(v.z, v.w, h, l);
            *(uint32_t*)(smem + MS_XH + (r * XLD + c + 2) * 2) = h;
            *(uint32_t*)(smem + MS_XL + (r * XLD + c + 2) * 2) = l;
        }
    }

    float acc[3][8][4];
    #pragma unroll
    for (int g = 0; g < 3; g++)
        #pragma unroll
        for (int n = 0; n < 8; n++)
            #pragma unroll
            for (int u = 0; u < 4; u++) acc[g][n][u] = 0.f;

    #pragma unroll 1
    for (int g = 0; g < 3; g++) {
        __syncthreads();   // X ready (iter 0) / prior W reads done
        // load W_g hi/lo into padded smem (256 k-rows x 128 n, stride 136)
        {
            const uint32_t* wh = g_whu + g * 16384;
            const uint32_t* wl = g_wlu + g * 16384;
            uint32_t* dh = (uint32_t*)(smem + MS_WH);
            uint32_t* dl = (uint32_t*)(smem + MS_WL);
            #pragma unroll
            for (int t = 0; t < 64; t++) {
                int idx = tid + t * 256;            // 16384 u32
                int r = idx >> 6, c = idx & 63;
                dh[r * 68 + c] = wh[idx];
                dl[r * 68 + c] = wl[idx];
            }
        }
        __syncthreads();

        #pragma unroll 1
        for (int sp = 0; sp < 3; sp++) {
            const uint32_t Ab = sb + ((sp == 2) ? MS_XL : MS_XH);
            const uint32_t Bb = sb + ((sp == 1) ? MS_WL : MS_WH);
            #pragma unroll
            for (int kt = 0; kt < 16; kt++) {
                uint32_t a[4];
                int row = wm * 16 + ((lg & 1) << 3) + li;
                int col = kt * 16 + ((lg >> 1) << 3);
                ldsm_x4(a, Ab + (row * XLD + col) * 2);
                #pragma unroll
                for (int n = 0; n < 8; n++) {
                    uint32_t bf[2];
                    int rowb = kt * 16 + ((lg & 1) << 3) + li;
                    int colb = wn * 64 + n * 8;
                    ldsm_x2t(bf, Bb + (rowb * LDT + colb) * 2);
                    mma_bf16(acc[g][n], a, bf);
                }
            }
        }
    }

    // ---- epilogue: out = sigmoid(a2+b2)*P + sigmoid(a3+b3)*tanh(a1+b1) ----
    #pragma unroll
    for (int n = 0; n < 8; n++) {
        int c = wn * 64 + n * 8 + qc2;
        float bb1x = b1[c], bb1y = b1[c + 1];
        float bb2x = b2[c], bb2y = b2[c + 1];
        float bb3x = b3[c], bb3y = b3[c + 1];
        #pragma unroll
        for (int half = 0; half < 2; half++) {
            size_t r = (size_t)row0 + wm * 16 + qr + half * 8;
            float2 pv = *(const float2*)(P + r * Dd + c);
            float a1x = acc[0][n][half * 2], a1y = acc[0][n][half * 2 + 1];
            float a2x = acc[1][n][half * 2], a2y = acc[1][n][half * 2 + 1];
            float a3x = acc[2][n][half * 2], a3y = acc[2][n][half * 2 + 1];
            float zx = tanhf(a1x + bb1x), zy = tanhf(a1y + bb1y);
            float rx = 1.f / (1.f + __expf(-(a2x + bb2x)));
            float ry = 1.f / (1.f + __expf(-(a2y + bb2y)));
            float fx = 1.f / (1.f + __expf(-(a3x + bb3x)));
            float fy = 1.f / (1.f + __expf(-(a3y + bb3y)));
            *(float2*)(out + r * Dd + c) =
                make_float2(rx * pv.x + fx * zx, ry * pv.y + fy * zy);
        }
    }
}

// ===========================================================================
extern "C" void kernel_launch(void* const* d_in, const int* in_sizes, int n_in,
                              void* d_out, int out_size) {
    const float* P  = (const float*)d_in[0];
    const float* w  = (const float*)d_in[1];
    const float* w1 = (const float*)d_in[2];
    const float* w2 = (const float*)d_in[3];
    const float* w3 = (const float*)d_in[4];
    const float* b1 = (const float*)d_in[5];
    const float* b2 = (const float*)d_in[6];
    const float* b3 = (const float*)d_in[7];
    float* out = (float*)d_out;

    cudaFuncSetAttribute(flash_hmma, cudaFuncAttributeMaxDynamicSharedMemorySize, FS_TOT);
    cudaFuncSetAttribute(mlp_hmma, cudaFuncAttributeMaxDynamicSharedMemorySize, MS_TOT);

    wsplit_kernel<<<64, 256>>>(w1, w2, w3);

    dim3 qb(32, 8);
    qa_kernel<<<NROWS / 8, qb>>>(P, w);

    dim3 fg(Nn / 128, Bsz);
    flash_hmma<<<fg, 256, FS_TOT>>>(P, w);

    mlp_hmma<<<NROWS / 64, 256, MS_TOT>>>(P, b1, b2, b3, out);
}